// round 15
// baseline (speedup 1.0000x reference)
#include <cuda_runtime.h>
#include <cuda_fp16.h>

// Shapes (fixed by the problem)
#define B_   64
#define N_   64
#define FIN  64
#define HID  256
#define OUT  64
#define T_   4
#define E_   4032   // N*(N-1)

typedef unsigned int u32;
typedef unsigned long long u64;

// Scratch (device globals: no allocation allowed)
__device__ __half g_Pa[T_ * B_ * N_ * HID];   // x @ w1[:, :64, :]          (8 MB)
__device__ __half g_Pb[T_ * B_ * N_ * HID];   // x @ w1[:, 64:, :] + b1     (8 MB)
__device__ float  g_agg[B_ * N_ * OUT];       // edge2node aggregate        (1 MB)

// ---------------- fp16 mma helper ----------------
__device__ __forceinline__ void mma_f16(float c[4], const u32 a[4], const u32 b[2]) {
    asm volatile(
        "mma.sync.aligned.m16n8k16.row.col.f32.f16.f16.f32 "
        "{%0,%1,%2,%3},{%4,%5,%6,%7},{%8,%9},{%0,%1,%2,%3};"
        : "+f"(c[0]), "+f"(c[1]), "+f"(c[2]), "+f"(c[3])
        : "r"(a[0]), "r"(a[1]), "r"(a[2]), "r"(a[3]), "r"(b[0]), "r"(b[1]));
}
// ---------------- packed f32x2 helpers ----------------
__device__ __forceinline__ u64 ffma2(u64 a, u64 b, u64 c) {
    u64 d;
    asm("fma.rn.f32x2 %0, %1, %2, %3;" : "=l"(d) : "l"(a), "l"(b), "l"(c));
    return d;
}
__device__ __forceinline__ u64 dup2(float a) {
    u64 d;
    asm("mov.b64 %0, {%1, %1};" : "=l"(d) : "f"(a));
    return d;
}
__device__ __forceinline__ u64 pack2(float lo, float hi) {
    u64 d;
    asm("mov.b64 %0, {%1, %2};" : "=l"(d) : "f"(lo), "f"(hi));
    return d;
}
__device__ __forceinline__ float2 unpack2(u64 v) {
    float2 r;
    asm("mov.b64 {%0, %1}, %2;" : "=f"(r.x), "=f"(r.y) : "l"(v));
    return r;
}

// ---------------------------------------------------------------------------
// K1 (fp16 tensor-core): X[4096,64] @ W_all[64,2048].
// Block = (rb: 64 rows, cb: 256 cols = one (t, part) slice). t=cb>>1, part=cb&1.
// A = fp16(x tile) [64][72]; B = fp16(w1 slice) [k=64][col=256 pad 264].
// Warp = 32-col group: 64M x 32N x 64K via ldmatrix + mma.m16n8k16.
// Epilogue: +b1 (part=1), cvt fp16, scattered half2 stores to g_Pa / g_Pb.
// ---------------------------------------------------------------------------
__global__ void __launch_bounds__(256) k1_proj(const float* __restrict__ x,
                                               const float* __restrict__ w1,
                                               const float* __restrict__ b1) {
    __shared__ __half sX[64 * 72];
    __shared__ __half sW[64 * 264];
    __shared__ float sb[256];
    const int tid = threadIdx.x;
    const int lane = tid & 31, wid = tid >> 5;
    const int rb = blockIdx.y, cb = blockIdx.x;
    const int t = cb >> 1, part = cb & 1;

    // stage x tile (fp32 -> fp16)
    const float4* x4 = (const float4*)x + rb * 1024;
#pragma unroll
    for (int i = 0; i < 4; i++) {
        int idx = i * 256 + tid;          // 1024 float4
        int row = idx >> 4, c4 = idx & 15;
        float4 v = x4[idx];
        __half2 h01 = __floats2half2_rn(v.x, v.y);
        __half2 h23 = __floats2half2_rn(v.z, v.w);
        __half2* dst = (__half2*)(sX + row * 72 + c4 * 4);
        dst[0] = h01; dst[1] = h23;
    }
    // stage w1 slice [k=64][h=256] (fp32 -> fp16)
    const float4* w4 = (const float4*)w1 + (t * 128 + part * 64) * 64;
#pragma unroll
    for (int i = 0; i < 16; i++) {
        int idx = i * 256 + tid;          // 4096 float4
        int k = idx >> 6, h4 = idx & 63;
        float4 v = w4[idx];
        __half2 h01 = __floats2half2_rn(v.x, v.y);
        __half2 h23 = __floats2half2_rn(v.z, v.w);
        __half2* dst = (__half2*)(sW + k * 264 + h4 * 4);
        dst[0] = h01; dst[1] = h23;
    }
    sb[tid] = part ? b1[t * 256 + tid] : 0.f;
    __syncthreads();

    const int g4 = lane >> 2, t4 = lane & 3;
    const int nbase = wid * 32;
    const u32 sX_u = (u32)__cvta_generic_to_shared(sX);
    const u32 sW_u = (u32)__cvta_generic_to_shared(sW);
    const u32 aAddr = sX_u +
        (u32)((((lane & 7) + ((lane >> 3) & 1) * 8) * 72 + (lane >> 4) * 8) * 2);
    const u32 bAddr = sW_u + (u32)(((lane & 15) * 264 + nbase) * 2);

    float c[16][4];
#pragma unroll
    for (int i = 0; i < 16; i++)
#pragma unroll
        for (int j = 0; j < 4; j++) c[i][j] = 0.f;

#pragma unroll
    for (int kc = 0; kc < 4; kc++) {
        u32 bf[4][2];
#pragma unroll
        for (int nt = 0; nt < 4; nt++) {
            u32 addr = bAddr + (u32)((kc * 16 * 264 + nt * 8) * 2);
            asm volatile("ldmatrix.sync.aligned.m8n8.x2.trans.shared.b16 {%0,%1}, [%2];"
                         : "=r"(bf[nt][0]), "=r"(bf[nt][1]) : "r"(addr));
        }
#pragma unroll
        for (int mt = 0; mt < 4; mt++) {
            u32 a[4];
            u32 addr = aAddr + (u32)((mt * 16 * 72 + kc * 16) * 2);
            asm volatile("ldmatrix.sync.aligned.m8n8.x4.shared.b16 {%0,%1,%2,%3}, [%4];"
                         : "=r"(a[0]), "=r"(a[1]), "=r"(a[2]), "=r"(a[3]) : "r"(addr));
#pragma unroll
            for (int nt = 0; nt < 4; nt++)
                mma_f16(c[mt * 4 + nt], a, bf[nt]);
        }
    }

    __half* base = (part ? g_Pb : g_Pa) + (t * 4096 + rb * 64) * 256;
#pragma unroll
    for (int mt = 0; mt < 4; mt++) {
#pragma unroll
        for (int nt = 0; nt < 4; nt++) {
            const float* cc = c[mt * 4 + nt];
            int col = nbase + nt * 8 + 2 * t4;
            float bb0 = sb[col], bb1 = sb[col + 1];
            int row0 = mt * 16 + g4;
            __half2 v0 = __floats2half2_rn(cc[0] + bb0, cc[1] + bb1);
            __half2 v1 = __floats2half2_rn(cc[2] + bb0, cc[3] + bb1);
            *(__half2*)(base + row0 * 256 + col) = v0;
            *(__half2*)(base + (row0 + 8) * 256 + col) = v1;
        }
    }
}

// ---------------------------------------------------------------------------
// K2 (dominant, fp16 tensor-core, 512 threads): block = (b, 4 receivers),
// loops t(4). sA [256 rows][264] half = relu(Pa[s]+Pb[r]); sB [256][72] half.
// Warp (r_local = wid&3, nq = wid>>2): 64M x 16N x 256K. Epilogue:
// relu(C+b2)*rel_type, shuffle-reduce over senders, register accumulate
// across t; one plain float2 store / owning lane at the end.
// ---------------------------------------------------------------------------
#define SA_K 264
#define SB_O 72
#define K2_SMEM (256 * SA_K * 2 + 256 * SB_O * 2 + 256 * 4 + 64 * 4)

__global__ void __launch_bounds__(512) k2_edge(const float* __restrict__ rel_type,
                                               const float* __restrict__ w2,
                                               const float* __restrict__ b2) {
    extern __shared__ __align__(16) char smraw[];
    __half* sA = (__half*)smraw;                              // [256][SA_K]
    __half* sB = (__half*)(smraw + 256 * SA_K * 2);           // [256][SB_O]
    float* rt_sm = (float*)(smraw + 256 * SA_K * 2 + 256 * SB_O * 2);  // [4][64]
    float* b2s = rt_sm + 256;                                 // [64]

    const int tid = threadIdx.x;
    const int lane = tid & 31, wid = tid >> 5;
    const int b = blockIdx.y, rbase = blockIdx.x * 4;
    const int r_local = wid & 3;      // receiver owned by this warp
    const int nq = wid >> 2;          // 16-col quarter of the 64 outputs
    const int g4 = lane >> 2, t4 = lane & 3;

    const u32 sA_u = (u32)__cvta_generic_to_shared(sA);
    const u32 sB_u = (u32)__cvta_generic_to_shared(sB);
    const u32 aAddr = sA_u +
        (u32)(((r_local * 64 + (lane & 7) + ((lane >> 3) & 1) * 8) * SA_K +
               (lane >> 4) * 8) * 2);
    const u32 bAddr = sB_u + (u32)(((lane & 15) * SB_O + nq * 16) * 2);

    float racc[2][2];
#pragma unroll
    for (int nt = 0; nt < 2; nt++) { racc[nt][0] = 0.f; racc[nt][1] = 0.f; }

    const __half2 z2 = __float2half2_rn(0.f);

    for (int t = 0; t < 4; t++) {
        __syncthreads();   // previous iteration's mma/epilogue done

        // ---- stage sB = fp16(w2[t]) as [k][o] ----
        const float4* w2t4 = (const float4*)(w2 + t * 16384);
#pragma unroll
        for (int i = 0; i < 8; i++) {
            int idx = i * 512 + tid;            // 4096 float4
            int k = idx >> 4, o4 = idx & 15;
            float4 w = w2t4[idx];
            __half2 h01 = __floats2half2_rn(w.x, w.y);
            __half2 h23 = __floats2half2_rn(w.z, w.w);
            __half2* dst = (__half2*)(sB + k * SB_O + o4 * 4);
            dst[0] = h01; dst[1] = h23;
        }
        // ---- stage rel_type for 4 receivers x 64 senders ----
        if (tid < 256) {
            int s = tid & 63, rl = tid >> 6;
            int r = rbase + rl;
            float v = 0.f;
            if (s != r) v = rel_type[(b * 4032 + s * 63 + r - (r > s ? 1 : 0)) * 4 + t];
            rt_sm[rl * 64 + s] = v;
        }
        if (tid < 64) b2s[tid] = b2[t * 64 + tid];

        // ---- build sA: row = rl*64+s, relu(Pa[s] + Pb[rbase+rl]) in fp16 ----
        const __half* PaH = g_Pa + (t * 4096 + b * 64) * 256;
        const __half* PbH = g_Pb + (t * 4096 + b * 64) * 256;
#pragma unroll
        for (int i = 0; i < 16; i++) {
            int grp = i * 512 + tid;            // 8192 groups of 8 halves
            int row = grp >> 5, c8 = grp & 31;
            int s = row & 63, rl = row >> 6;
            uint4 pa = *(const uint4*)(PaH + s * 256 + c8 * 8);
            uint4 pb = *(const uint4*)(PbH + (rbase + rl) * 256 + c8 * 8);
            uint4 o;
            __half2 v;
            v = __hmax2(__hadd2(*(__half2*)&pa.x, *(__half2*)&pb.x), z2); o.x = *(u32*)&v;
            v = __hmax2(__hadd2(*(__half2*)&pa.y, *(__half2*)&pb.y), z2); o.y = *(u32*)&v;
            v = __hmax2(__hadd2(*(__half2*)&pa.z, *(__half2*)&pb.z), z2); o.z = *(u32*)&v;
            v = __hmax2(__hadd2(*(__half2*)&pa.w, *(__half2*)&pb.w), z2); o.w = *(u32*)&v;
            *(uint4*)(sA + row * SA_K + c8 * 8) = o;
        }
        __syncthreads();

        // ---- 64x16x256 warp GEMM: 4mt x 2nt m16n8k16 tiles, 16 k-chunks ----
        float c[8][4];
#pragma unroll
        for (int i = 0; i < 8; i++)
#pragma unroll
            for (int j = 0; j < 4; j++) c[i][j] = 0.f;

#pragma unroll
        for (int kc = 0; kc < 16; kc++) {
            u32 bf[2][2];
#pragma unroll
            for (int nt = 0; nt < 2; nt++) {
                u32 addr = bAddr + (u32)((kc * 16 * SB_O + nt * 8) * 2);
                asm volatile(
                    "ldmatrix.sync.aligned.m8n8.x2.trans.shared.b16 {%0,%1}, [%2];"
                    : "=r"(bf[nt][0]), "=r"(bf[nt][1]) : "r"(addr));
            }
#pragma unroll
            for (int mt = 0; mt < 4; mt++) {
                u32 a[4];
                u32 addr = aAddr + (u32)((mt * 16 * SA_K + kc * 16) * 2);
                asm volatile(
                    "ldmatrix.sync.aligned.m8n8.x4.shared.b16 {%0,%1,%2,%3}, [%4];"
                    : "=r"(a[0]), "=r"(a[1]), "=r"(a[2]), "=r"(a[3]) : "r"(addr));
#pragma unroll
                for (int nt = 0; nt < 2; nt++)
                    mma_f16(c[mt * 2 + nt], a, bf[nt]);
            }
        }

        // ---- epilogue: relu(C + b2)*rt, reduce over senders, accum in regs ----
        float rtv[4][2];
#pragma unroll
        for (int mt = 0; mt < 4; mt++) {
            rtv[mt][0] = rt_sm[r_local * 64 + mt * 16 + g4];
            rtv[mt][1] = rt_sm[r_local * 64 + mt * 16 + g4 + 8];
        }
#pragma unroll
        for (int nt = 0; nt < 2; nt++) {
            int col = nq * 16 + nt * 8 + 2 * t4;
            float bb0 = b2s[col], bb1 = b2s[col + 1];
            float p0 = 0.f, p1 = 0.f;
#pragma unroll
            for (int mt = 0; mt < 4; mt++) {
                const float* cc = c[mt * 2 + nt];
                p0 += fmaxf(cc[0] + bb0, 0.f) * rtv[mt][0];
                p1 += fmaxf(cc[1] + bb1, 0.f) * rtv[mt][0];
                p0 += fmaxf(cc[2] + bb0, 0.f) * rtv[mt][1];
                p1 += fmaxf(cc[3] + bb1, 0.f) * rtv[mt][1];
            }
#pragma unroll
            for (int off = 4; off < 32; off <<= 1) {
                p0 += __shfl_xor_sync(0xffffffffu, p0, off);
                p1 += __shfl_xor_sync(0xffffffffu, p1, off);
            }
            racc[nt][0] += p0;
            racc[nt][1] += p1;
        }
    }

    // ---- final store: each (b, r, col) owned by exactly one warp ----
    if (lane < 4) {   // g4 == 0 lanes, t4 = lane
        float* dst = g_agg + (b * 64 + rbase + r_local) * 64 + nq * 16 + 2 * t4;
#pragma unroll
        for (int nt = 0; nt < 2; nt++)
            *(float2*)(dst + nt * 8) = make_float2(racc[nt][0], racc[nt][1]);
    }
}

// ---------------------------------------------------------------------------
// K3: output MLP, f32x2 packed fma, 128 blocks x 32 rows, 256 threads.
// ---------------------------------------------------------------------------
#define HPAD 260
#define K3_SMEM ((32 * 128 + 2 * 32 * HPAD) * 4)

__global__ void __launch_bounds__(256) k3_out(const float* __restrict__ x,
                                              const float* __restrict__ ow1,
                                              const float* __restrict__ ob1,
                                              const float* __restrict__ ow2,
                                              const float* __restrict__ ob2,
                                              const float* __restrict__ ow3,
                                              const float* __restrict__ ob3,
                                              float* __restrict__ out) {
    extern __shared__ __align__(16) float sm3[];
    float* sAug = sm3;                 // [32][128]
    float* sH = sm3 + 32 * 128;        // [32][HPAD]
    float* sH2 = sH + 32 * HPAD;       // [32][HPAD]
    const int tid = threadIdx.x;
    const int base = blockIdx.x * 32;

#pragma unroll
    for (int i = 0; i < 16; i++) {
        int idx = tid + i * 256;           // 4096
        int row = idx >> 7, c = idx & 127;
        float v = (c < 64) ? x[(base + row) * 64 + c]
                           : g_agg[(base + row) * 64 + (c - 64)];
        sAug[idx] = v;
    }
    __syncthreads();

    const int cg = tid & 63, rg = tid >> 6;   // 64 col-groups x 4 row-groups(8 rows)

    {   // stage 1: 128 -> 256
        u64 acc[8][2];
#pragma unroll
        for (int r = 0; r < 8; r++) { acc[r][0] = 0ull; acc[r][1] = 0ull; }
#pragma unroll 4
        for (int k = 0; k < 128; k++) {
            float4 w = *((const float4*)(ow1 + k * 256) + cg);
            u64 w01 = pack2(w.x, w.y), w23 = pack2(w.z, w.w);
#pragma unroll
            for (int r = 0; r < 8; r++) {
                u64 a = dup2(sAug[(rg * 8 + r) * 128 + k]);
                acc[r][0] = ffma2(a, w01, acc[r][0]);
                acc[r][1] = ffma2(a, w23, acc[r][1]);
            }
        }
        float4 bb = *((const float4*)ob1 + cg);
#pragma unroll
        for (int r = 0; r < 8; r++) {
            float2 v01 = unpack2(acc[r][0]), v23 = unpack2(acc[r][1]);
            float* dst = sH + (rg * 8 + r) * HPAD + cg * 4;
            dst[0] = fmaxf(v01.x + bb.x, 0.f);
            dst[1] = fmaxf(v01.y + bb.y, 0.f);
            dst[2] = fmaxf(v23.x + bb.z, 0.f);
            dst[3] = fmaxf(v23.y + bb.w, 0.f);
        }
    }
    __syncthreads();

    {   // stage 2: 256 -> 256
        u64 acc[8][2];
#pragma unroll
        for (int r = 0; r < 8; r++) { acc[r][0] = 0ull; acc[r][1] = 0ull; }
#pragma unroll 4
        for (int k = 0; k < 256; k++) {
            float4 w = *((const float4*)(ow2 + k * 256) + cg);
            u64 w01 = pack2(w.x, w.y), w23 = pack2(w.z, w.w);
#pragma unroll
            for (int r = 0; r < 8; r++) {
                u64 a = dup2(sH[(rg * 8 + r) * HPAD + k]);
                acc[r][0] = ffma2(a, w01, acc[r][0]);
                acc[r][1] = ffma2(a, w23, acc[r][1]);
            }
        }
        float4 bb = *((const float4*)ob2 + cg);
#pragma unroll
        for (int r = 0; r < 8; r++) {
            float2 v01 = unpack2(acc[r][0]), v23 = unpack2(acc[r][1]);
            float* dst = sH2 + (rg * 8 + r) * HPAD + cg * 4;
            dst[0] = fmaxf(v01.x + bb.x, 0.f);
            dst[1] = fmaxf(v01.y + bb.y, 0.f);
            dst[2] = fmaxf(v23.x + bb.z, 0.f);
            dst[3] = fmaxf(v23.y + bb.w, 0.f);
        }
    }
    __syncthreads();

    {   // stage 3: 256 -> 64 (fp32, full precision on the final layer)
        const int cg2 = tid & 15, rt = tid >> 4;   // 16 col-groups x 16, 2 rows each
        u64 acc[2][2];
        acc[0][0] = acc[0][1] = acc[1][0] = acc[1][1] = 0ull;
#pragma unroll 4
        for (int k = 0; k < 256; k++) {
            float4 w = *((const float4*)(ow3 + k * 64) + cg2);
            u64 w01 = pack2(w.x, w.y), w23 = pack2(w.z, w.w);
            u64 a0 = dup2(sH2[rt * HPAD + k]);
            u64 a1 = dup2(sH2[(rt + 16) * HPAD + k]);
            acc[0][0] = ffma2(a0, w01, acc[0][0]);
            acc[0][1] = ffma2(a0, w23, acc[0][1]);
            acc[1][0] = ffma2(a1, w01, acc[1][0]);
            acc[1][1] = ffma2(a1, w23, acc[1][1]);
        }
        float4 bb = *((const float4*)ob3 + cg2);
#pragma unroll
        for (int rr = 0; rr < 2; rr++) {
            float2 v01 = unpack2(acc[rr][0]), v23 = unpack2(acc[rr][1]);
            float4 v = make_float4(v01.x + bb.x, v01.y + bb.y,
                                   v23.x + bb.z, v23.y + bb.w);
            *((float4*)(out + (base + rt + rr * 16) * 64) + cg2) = v;
        }
    }
}

// ---------------------------------------------------------------------------
extern "C" void kernel_launch(void* const* d_in, const int* in_sizes, int n_in,
                              void* d_out, int out_size) {
    const float* x        = (const float*)d_in[0];
    const float* rel_type = (const float*)d_in[1];
    // d_in[2]=rel_rec, d_in[3]=rel_send: structure is analytic, unused
    const float* w1  = (const float*)d_in[4];
    const float* b1  = (const float*)d_in[5];
    const float* w2  = (const float*)d_in[6];
    const float* b2  = (const float*)d_in[7];
    const float* ow1 = (const float*)d_in[8];
    const float* ob1 = (const float*)d_in[9];
    const float* ow2 = (const float*)d_in[10];
    const float* ob2 = (const float*)d_in[11];
    const float* ow3 = (const float*)d_in[12];
    const float* ob3 = (const float*)d_in[13];
    float* out = (float*)d_out;

    cudaFuncSetAttribute(k2_edge, cudaFuncAttributeMaxDynamicSharedMemorySize, K2_SMEM);
    cudaFuncSetAttribute(k3_out, cudaFuncAttributeMaxDynamicSharedMemorySize, K3_SMEM);

    k1_proj<<<dim3(8, 64), 256>>>(x, w1, b1);
    k2_edge<<<dim3(16, 64), 512, K2_SMEM>>>(rel_type, w2, b2);
    k3_out<<<128, 256, K3_SMEM>>>(x, ow1, ob1, ow2, ob2, ow3, ob3, out);
}

// round 16
// speedup vs baseline: 1.0009x; 1.0009x over previous
#include <cuda_runtime.h>
#include <cuda_fp16.h>

// Shapes (fixed by the problem)
#define B_   64
#define N_   64
#define FIN  64
#define HID  256
#define OUT  64
#define T_   4
#define E_   4032   // N*(N-1)

typedef unsigned int u32;
typedef unsigned long long u64;

// Scratch (device globals: no allocation allowed)
__device__ __half g_Pa[T_ * B_ * N_ * HID];   // x @ w1[:, :64, :]          (8 MB)
__device__ __half g_Pb[T_ * B_ * N_ * HID];   // x @ w1[:, 64:, :] + b1     (8 MB)
__device__ float  g_agg[B_ * N_ * OUT];       // edge2node aggregate        (1 MB)

// ---------------- fp16 mma helper ----------------
__device__ __forceinline__ void mma_f16(float c[4], const u32 a[4], const u32 b[2]) {
    asm volatile(
        "mma.sync.aligned.m16n8k16.row.col.f32.f16.f16.f32 "
        "{%0,%1,%2,%3},{%4,%5,%6,%7},{%8,%9},{%0,%1,%2,%3};"
        : "+f"(c[0]), "+f"(c[1]), "+f"(c[2]), "+f"(c[3])
        : "r"(a[0]), "r"(a[1]), "r"(a[2]), "r"(a[3]), "r"(b[0]), "r"(b[1]));
}
// ---------------- packed f32x2 helpers ----------------
__device__ __forceinline__ u64 ffma2(u64 a, u64 b, u64 c) {
    u64 d;
    asm("fma.rn.f32x2 %0, %1, %2, %3;" : "=l"(d) : "l"(a), "l"(b), "l"(c));
    return d;
}
__device__ __forceinline__ u64 dup2(float a) {
    u64 d;
    asm("mov.b64 %0, {%1, %1};" : "=l"(d) : "f"(a));
    return d;
}
__device__ __forceinline__ u64 pack2(float lo, float hi) {
    u64 d;
    asm("mov.b64 %0, {%1, %2};" : "=l"(d) : "f"(lo), "f"(hi));
    return d;
}
__device__ __forceinline__ float2 unpack2(u64 v) {
    float2 r;
    asm("mov.b64 {%0, %1}, %2;" : "=f"(r.x), "=f"(r.y) : "l"(v));
    return r;
}

// ---------------------------------------------------------------------------
// K1 (fp16 tensor-core): X[4096,64] @ W_all[64,2048].
// Block = (rb: 64 rows, cb: 256 cols = one (t, part) slice). t=cb>>1, part=cb&1.
// A = fp16(x tile) [64][72]; B = fp16(w1 slice) [k=64][col=256 pad 264].
// Warp = 32-col group: 64M x 32N x 64K via ldmatrix + mma.m16n8k16.
// Epilogue: +b1 (part=1), cvt fp16, scattered half2 stores to g_Pa / g_Pb.
// ---------------------------------------------------------------------------
__global__ void __launch_bounds__(256) k1_proj(const float* __restrict__ x,
                                               const float* __restrict__ w1,
                                               const float* __restrict__ b1) {
    __shared__ __half sX[64 * 72];
    __shared__ __half sW[64 * 264];
    __shared__ float sb[256];
    const int tid = threadIdx.x;
    const int lane = tid & 31, wid = tid >> 5;
    const int rb = blockIdx.y, cb = blockIdx.x;
    const int t = cb >> 1, part = cb & 1;

    // stage x tile (fp32 -> fp16)
    const float4* x4 = (const float4*)x + rb * 1024;
#pragma unroll
    for (int i = 0; i < 4; i++) {
        int idx = i * 256 + tid;          // 1024 float4
        int row = idx >> 4, c4 = idx & 15;
        float4 v = x4[idx];
        __half2 h01 = __floats2half2_rn(v.x, v.y);
        __half2 h23 = __floats2half2_rn(v.z, v.w);
        __half2* dst = (__half2*)(sX + row * 72 + c4 * 4);
        dst[0] = h01; dst[1] = h23;
    }
    // stage w1 slice [k=64][h=256] (fp32 -> fp16)
    const float4* w4 = (const float4*)w1 + (t * 128 + part * 64) * 64;
#pragma unroll
    for (int i = 0; i < 16; i++) {
        int idx = i * 256 + tid;          // 4096 float4
        int k = idx >> 6, h4 = idx & 63;
        float4 v = w4[idx];
        __half2 h01 = __floats2half2_rn(v.x, v.y);
        __half2 h23 = __floats2half2_rn(v.z, v.w);
        __half2* dst = (__half2*)(sW + k * 264 + h4 * 4);
        dst[0] = h01; dst[1] = h23;
    }
    sb[tid] = part ? b1[t * 256 + tid] : 0.f;
    __syncthreads();

    const int g4 = lane >> 2, t4 = lane & 3;
    const int nbase = wid * 32;
    const u32 sX_u = (u32)__cvta_generic_to_shared(sX);
    const u32 sW_u = (u32)__cvta_generic_to_shared(sW);
    const u32 aAddr = sX_u +
        (u32)((((lane & 7) + ((lane >> 3) & 1) * 8) * 72 + (lane >> 4) * 8) * 2);
    const u32 bAddr = sW_u + (u32)(((lane & 15) * 264 + nbase) * 2);

    float c[16][4];
#pragma unroll
    for (int i = 0; i < 16; i++)
#pragma unroll
        for (int j = 0; j < 4; j++) c[i][j] = 0.f;

#pragma unroll
    for (int kc = 0; kc < 4; kc++) {
        u32 bf[4][2];
#pragma unroll
        for (int nt = 0; nt < 4; nt++) {
            u32 addr = bAddr + (u32)((kc * 16 * 264 + nt * 8) * 2);
            asm volatile("ldmatrix.sync.aligned.m8n8.x2.trans.shared.b16 {%0,%1}, [%2];"
                         : "=r"(bf[nt][0]), "=r"(bf[nt][1]) : "r"(addr));
        }
#pragma unroll
        for (int mt = 0; mt < 4; mt++) {
            u32 a[4];
            u32 addr = aAddr + (u32)((mt * 16 * 72 + kc * 16) * 2);
            asm volatile("ldmatrix.sync.aligned.m8n8.x4.shared.b16 {%0,%1,%2,%3}, [%4];"
                         : "=r"(a[0]), "=r"(a[1]), "=r"(a[2]), "=r"(a[3]) : "r"(addr));
#pragma unroll
            for (int nt = 0; nt < 4; nt++)
                mma_f16(c[mt * 4 + nt], a, bf[nt]);
        }
    }

    __half* base = (part ? g_Pb : g_Pa) + (t * 4096 + rb * 64) * 256;
#pragma unroll
    for (int mt = 0; mt < 4; mt++) {
#pragma unroll
        for (int nt = 0; nt < 4; nt++) {
            const float* cc = c[mt * 4 + nt];
            int col = nbase + nt * 8 + 2 * t4;
            float bb0 = sb[col], bb1 = sb[col + 1];
            int row0 = mt * 16 + g4;
            __half2 v0 = __floats2half2_rn(cc[0] + bb0, cc[1] + bb1);
            __half2 v1 = __floats2half2_rn(cc[2] + bb0, cc[3] + bb1);
            *(__half2*)(base + row0 * 256 + col) = v0;
            *(__half2*)(base + (row0 + 8) * 256 + col) = v1;
        }
    }
}

// ---------------------------------------------------------------------------
// K2 (dominant, fp16 tensor-core, 512 threads): block = (b, 4 receivers),
// loops t(4). sA [256 rows][264] half = relu(Pa[s]+Pb[r]); sB [256][72] half.
// Warp (r_local = wid&3, nq = wid>>2): 64M x 16N x 256K. Epilogue:
// relu(C+b2)*rel_type, shuffle-reduce over senders, register accumulate
// across t; one plain float2 store / owning lane at the end.
// ---------------------------------------------------------------------------
#define SA_K 264
#define SB_O 72
#define K2_SMEM (256 * SA_K * 2 + 256 * SB_O * 2 + 256 * 4 + 64 * 4)

__global__ void __launch_bounds__(512) k2_edge(const float* __restrict__ rel_type,
                                               const float* __restrict__ w2,
                                               const float* __restrict__ b2) {
    extern __shared__ __align__(16) char smraw[];
    __half* sA = (__half*)smraw;                              // [256][SA_K]
    __half* sB = (__half*)(smraw + 256 * SA_K * 2);           // [256][SB_O]
    float* rt_sm = (float*)(smraw + 256 * SA_K * 2 + 256 * SB_O * 2);  // [4][64]
    float* b2s = rt_sm + 256;                                 // [64]

    const int tid = threadIdx.x;
    const int lane = tid & 31, wid = tid >> 5;
    const int b = blockIdx.y, rbase = blockIdx.x * 4;
    const int r_local = wid & 3;      // receiver owned by this warp
    const int nq = wid >> 2;          // 16-col quarter of the 64 outputs
    const int g4 = lane >> 2, t4 = lane & 3;

    const u32 sA_u = (u32)__cvta_generic_to_shared(sA);
    const u32 sB_u = (u32)__cvta_generic_to_shared(sB);
    const u32 aAddr = sA_u +
        (u32)(((r_local * 64 + (lane & 7) + ((lane >> 3) & 1) * 8) * SA_K +
               (lane >> 4) * 8) * 2);
    const u32 bAddr = sB_u + (u32)(((lane & 15) * SB_O + nq * 16) * 2);

    float racc[2][2];
#pragma unroll
    for (int nt = 0; nt < 2; nt++) { racc[nt][0] = 0.f; racc[nt][1] = 0.f; }

    const __half2 z2 = __float2half2_rn(0.f);

    for (int t = 0; t < 4; t++) {
        __syncthreads();   // previous iteration's mma/epilogue done

        // ---- stage sB = fp16(w2[t]) as [k][o] ----
        const float4* w2t4 = (const float4*)(w2 + t * 16384);
#pragma unroll
        for (int i = 0; i < 8; i++) {
            int idx = i * 512 + tid;            // 4096 float4
            int k = idx >> 4, o4 = idx & 15;
            float4 w = w2t4[idx];
            __half2 h01 = __floats2half2_rn(w.x, w.y);
            __half2 h23 = __floats2half2_rn(w.z, w.w);
            __half2* dst = (__half2*)(sB + k * SB_O + o4 * 4);
            dst[0] = h01; dst[1] = h23;
        }
        // ---- stage rel_type for 4 receivers x 64 senders ----
        if (tid < 256) {
            int s = tid & 63, rl = tid >> 6;
            int r = rbase + rl;
            float v = 0.f;
            if (s != r) v = rel_type[(b * 4032 + s * 63 + r - (r > s ? 1 : 0)) * 4 + t];
            rt_sm[rl * 64 + s] = v;
        }
        if (tid < 64) b2s[tid] = b2[t * 64 + tid];

        // ---- build sA: row = rl*64+s, relu(Pa[s] + Pb[rbase+rl]) in fp16 ----
        const __half* PaH = g_Pa + (t * 4096 + b * 64) * 256;
        const __half* PbH = g_Pb + (t * 4096 + b * 64) * 256;
#pragma unroll
        for (int i = 0; i < 16; i++) {
            int grp = i * 512 + tid;            // 8192 groups of 8 halves
            int row = grp >> 5, c8 = grp & 31;
            int s = row & 63, rl = row >> 6;
            uint4 pa = *(const uint4*)(PaH + s * 256 + c8 * 8);
            uint4 pb = *(const uint4*)(PbH + (rbase + rl) * 256 + c8 * 8);
            uint4 o;
            __half2 v;
            v = __hmax2(__hadd2(*(__half2*)&pa.x, *(__half2*)&pb.x), z2); o.x = *(u32*)&v;
            v = __hmax2(__hadd2(*(__half2*)&pa.y, *(__half2*)&pb.y), z2); o.y = *(u32*)&v;
            v = __hmax2(__hadd2(*(__half2*)&pa.z, *(__half2*)&pb.z), z2); o.z = *(u32*)&v;
            v = __hmax2(__hadd2(*(__half2*)&pa.w, *(__half2*)&pb.w), z2); o.w = *(u32*)&v;
            *(uint4*)(sA + row * SA_K + c8 * 8) = o;
        }
        __syncthreads();

        // ---- 64x16x256 warp GEMM: 4mt x 2nt m16n8k16 tiles, 16 k-chunks ----
        float c[8][4];
#pragma unroll
        for (int i = 0; i < 8; i++)
#pragma unroll
            for (int j = 0; j < 4; j++) c[i][j] = 0.f;

#pragma unroll
        for (int kc = 0; kc < 16; kc++) {
            u32 bf[2][2];
#pragma unroll
            for (int nt = 0; nt < 2; nt++) {
                u32 addr = bAddr + (u32)((kc * 16 * SB_O + nt * 8) * 2);
                asm volatile(
                    "ldmatrix.sync.aligned.m8n8.x2.trans.shared.b16 {%0,%1}, [%2];"
                    : "=r"(bf[nt][0]), "=r"(bf[nt][1]) : "r"(addr));
            }
#pragma unroll
            for (int mt = 0; mt < 4; mt++) {
                u32 a[4];
                u32 addr = aAddr + (u32)((mt * 16 * SA_K + kc * 16) * 2);
                asm volatile(
                    "ldmatrix.sync.aligned.m8n8.x4.shared.b16 {%0,%1,%2,%3}, [%4];"
                    : "=r"(a[0]), "=r"(a[1]), "=r"(a[2]), "=r"(a[3]) : "r"(addr));
#pragma unroll
                for (int nt = 0; nt < 2; nt++)
                    mma_f16(c[mt * 2 + nt], a, bf[nt]);
            }
        }

        // ---- epilogue: relu(C + b2)*rt, reduce over senders, accum in regs ----
        float rtv[4][2];
#pragma unroll
        for (int mt = 0; mt < 4; mt++) {
            rtv[mt][0] = rt_sm[r_local * 64 + mt * 16 + g4];
            rtv[mt][1] = rt_sm[r_local * 64 + mt * 16 + g4 + 8];
        }
#pragma unroll
        for (int nt = 0; nt < 2; nt++) {
            int col = nq * 16 + nt * 8 + 2 * t4;
            float bb0 = b2s[col], bb1 = b2s[col + 1];
            float p0 = 0.f, p1 = 0.f;
#pragma unroll
            for (int mt = 0; mt < 4; mt++) {
                const float* cc = c[mt * 2 + nt];
                p0 += fmaxf(cc[0] + bb0, 0.f) * rtv[mt][0];
                p1 += fmaxf(cc[1] + bb1, 0.f) * rtv[mt][0];
                p0 += fmaxf(cc[2] + bb0, 0.f) * rtv[mt][1];
                p1 += fmaxf(cc[3] + bb1, 0.f) * rtv[mt][1];
            }
#pragma unroll
            for (int off = 4; off < 32; off <<= 1) {
                p0 += __shfl_xor_sync(0xffffffffu, p0, off);
                p1 += __shfl_xor_sync(0xffffffffu, p1, off);
            }
            racc[nt][0] += p0;
            racc[nt][1] += p1;
        }
    }

    // ---- final store: each (b, r, col) owned by exactly one warp ----
    if (lane < 4) {   // g4 == 0 lanes, t4 = lane
        float* dst = g_agg + (b * 64 + rbase + r_local) * 64 + nq * 16 + 2 * t4;
#pragma unroll
        for (int nt = 0; nt < 2; nt++)
            *(float2*)(dst + nt * 8) = make_float2(racc[nt][0], racc[nt][1]);
    }
}

// ---------------------------------------------------------------------------
// K3: output MLP, f32x2 packed fma, 128 blocks x 32 rows, 256 threads.
// ---------------------------------------------------------------------------
#define HPAD 260
#define K3_SMEM ((32 * 128 + 2 * 32 * HPAD) * 4)

__global__ void __launch_bounds__(256) k3_out(const float* __restrict__ x,
                                              const float* __restrict__ ow1,
                                              const float* __restrict__ ob1,
                                              const float* __restrict__ ow2,
                                              const float* __restrict__ ob2,
                                              const float* __restrict__ ow3,
                                              const float* __restrict__ ob3,
                                              float* __restrict__ out) {
    extern __shared__ __align__(16) float sm3[];
    float* sAug = sm3;                 // [32][128]
    float* sH = sm3 + 32 * 128;        // [32][HPAD]
    float* sH2 = sH + 32 * HPAD;       // [32][HPAD]
    const int tid = threadIdx.x;
    const int base = blockIdx.x * 32;

#pragma unroll
    for (int i = 0; i < 16; i++) {
        int idx = tid + i * 256;           // 4096
        int row = idx >> 7, c = idx & 127;
        float v = (c < 64) ? x[(base + row) * 64 + c]
                           : g_agg[(base + row) * 64 + (c - 64)];
        sAug[idx] = v;
    }
    __syncthreads();

    const int cg = tid & 63, rg = tid >> 6;   // 64 col-groups x 4 row-groups(8 rows)

    {   // stage 1: 128 -> 256
        u64 acc[8][2];
#pragma unroll
        for (int r = 0; r < 8; r++) { acc[r][0] = 0ull; acc[r][1] = 0ull; }
#pragma unroll 4
        for (int k = 0; k < 128; k++) {
            float4 w = *((const float4*)(ow1 + k * 256) + cg);
            u64 w01 = pack2(w.x, w.y), w23 = pack2(w.z, w.w);
#pragma unroll
            for (int r = 0; r < 8; r++) {
                u64 a = dup2(sAug[(rg * 8 + r) * 128 + k]);
                acc[r][0] = ffma2(a, w01, acc[r][0]);
                acc[r][1] = ffma2(a, w23, acc[r][1]);
            }
        }
        float4 bb = *((const float4*)ob1 + cg);
#pragma unroll
        for (int r = 0; r < 8; r++) {
            float2 v01 = unpack2(acc[r][0]), v23 = unpack2(acc[r][1]);
            float* dst = sH + (rg * 8 + r) * HPAD + cg * 4;
            dst[0] = fmaxf(v01.x + bb.x, 0.f);
            dst[1] = fmaxf(v01.y + bb.y, 0.f);
            dst[2] = fmaxf(v23.x + bb.z, 0.f);
            dst[3] = fmaxf(v23.y + bb.w, 0.f);
        }
    }
    __syncthreads();

    {   // stage 2: 256 -> 256
        u64 acc[8][2];
#pragma unroll
        for (int r = 0; r < 8; r++) { acc[r][0] = 0ull; acc[r][1] = 0ull; }
#pragma unroll 4
        for (int k = 0; k < 256; k++) {
            float4 w = *((const float4*)(ow2 + k * 256) + cg);
            u64 w01 = pack2(w.x, w.y), w23 = pack2(w.z, w.w);
#pragma unroll
            for (int r = 0; r < 8; r++) {
                u64 a = dup2(sH[(rg * 8 + r) * HPAD + k]);
                acc[r][0] = ffma2(a, w01, acc[r][0]);
                acc[r][1] = ffma2(a, w23, acc[r][1]);
            }
        }
        float4 bb = *((const float4*)ob2 + cg);
#pragma unroll
        for (int r = 0; r < 8; r++) {
            float2 v01 = unpack2(acc[r][0]), v23 = unpack2(acc[r][1]);
            float* dst = sH2 + (rg * 8 + r) * HPAD + cg * 4;
            dst[0] = fmaxf(v01.x + bb.x, 0.f);
            dst[1] = fmaxf(v01.y + bb.y, 0.f);
            dst[2] = fmaxf(v23.x + bb.z, 0.f);
            dst[3] = fmaxf(v23.y + bb.w, 0.f);
        }
    }
    __syncthreads();

    {   // stage 3: 256 -> 64 (fp32, full precision on the final layer)
        const int cg2 = tid & 15, rt = tid >> 4;   // 16 col-groups x 16, 2 rows each
        u64 acc[2][2];
        acc[0][0] = acc[0][1] = acc[1][0] = acc[1][1] = 0ull;
#pragma unroll 4
        for (int k = 0; k < 256; k++) {
            float4 w = *((const float4*)(ow3 + k * 64) + cg2);
            u64 w01 = pack2(w.x, w.y), w23 = pack2(w.z, w.w);
            u64 a0 = dup2(sH2[rt * HPAD + k]);
            u64 a1 = dup2(sH2[(rt + 16) * HPAD + k]);
            acc[0][0] = ffma2(a0, w01, acc[0][0]);
            acc[0][1] = ffma2(a0, w23, acc[0][1]);
            acc[1][0] = ffma2(a1, w01, acc[1][0]);
            acc[1][1] = ffma2(a1, w23, acc[1][1]);
        }
        float4 bb = *((const float4*)ob3 + cg2);
#pragma unroll
        for (int rr = 0; rr < 2; rr++) {
            float2 v01 = unpack2(acc[rr][0]), v23 = unpack2(acc[rr][1]);
            float4 v = make_float4(v01.x + bb.x, v01.y + bb.y,
                                   v23.x + bb.z, v23.y + bb.w);
            *((float4*)(out + (base + rt + rr * 16) * 64) + cg2) = v;
        }
    }
}

// ---------------------------------------------------------------------------
extern "C" void kernel_launch(void* const* d_in, const int* in_sizes, int n_in,
                              void* d_out, int out_size) {
    const float* x        = (const float*)d_in[0];
    const float* rel_type = (const float*)d_in[1];
    // d_in[2]=rel_rec, d_in[3]=rel_send: structure is analytic, unused
    const float* w1  = (const float*)d_in[4];
    const float* b1  = (const float*)d_in[5];
    const float* w2  = (const float*)d_in[6];
    const float* b2  = (const float*)d_in[7];
    const float* ow1 = (const float*)d_in[8];
    const float* ob1 = (const float*)d_in[9];
    const float* ow2 = (const float*)d_in[10];
    const float* ob2 = (const float*)d_in[11];
    const float* ow3 = (const float*)d_in[12];
    const float* ob3 = (const float*)d_in[13];
    float* out = (float*)d_out;

    cudaFuncSetAttribute(k2_edge, cudaFuncAttributeMaxDynamicSharedMemorySize, K2_SMEM);
    cudaFuncSetAttribute(k3_out, cudaFuncAttributeMaxDynamicSharedMemorySize, K3_SMEM);

    k1_proj<<<dim3(8, 64), 256>>>(x, w1, b1);
    k2_edge<<<dim3(16, 64), 512, K2_SMEM>>>(rel_type, w2, b2);
    k3_out<<<128, 256, K3_SMEM>>>(x, ow1, ob1, ow2, ob2, ow3, ob3, out);
}

// round 17
// speedup vs baseline: 1.0014x; 1.0005x over previous
#include <cuda_runtime.h>
#include <cuda_fp16.h>

// Shapes (fixed by the problem)
#define B_   64
#define N_   64
#define FIN  64
#define HID  256
#define OUT  64
#define T_   4
#define E_   4032   // N*(N-1)

typedef unsigned int u32;
typedef unsigned long long u64;

// Scratch (device globals: no allocation allowed)
__device__ __half g_Pa[T_ * B_ * N_ * HID];   // x @ w1[:, :64, :]          (8 MB)
__device__ __half g_Pb[T_ * B_ * N_ * HID];   // x @ w1[:, 64:, :] + b1     (8 MB)
__device__ float  g_agg[B_ * N_ * OUT];       // edge2node aggregate        (1 MB)

// ---------------- fp16 mma helper ----------------
__device__ __forceinline__ void mma_f16(float c[4], const u32 a[4], const u32 b[2]) {
    asm volatile(
        "mma.sync.aligned.m16n8k16.row.col.f32.f16.f16.f32 "
        "{%0,%1,%2,%3},{%4,%5,%6,%7},{%8,%9},{%0,%1,%2,%3};"
        : "+f"(c[0]), "+f"(c[1]), "+f"(c[2]), "+f"(c[3])
        : "r"(a[0]), "r"(a[1]), "r"(a[2]), "r"(a[3]), "r"(b[0]), "r"(b[1]));
}
// ---------------- packed f32x2 helpers ----------------
__device__ __forceinline__ u64 ffma2(u64 a, u64 b, u64 c) {
    u64 d;
    asm("fma.rn.f32x2 %0, %1, %2, %3;" : "=l"(d) : "l"(a), "l"(b), "l"(c));
    return d;
}
__device__ __forceinline__ u64 dup2(float a) {
    u64 d;
    asm("mov.b64 %0, {%1, %1};" : "=l"(d) : "f"(a));
    return d;
}
__device__ __forceinline__ u64 pack2(float lo, float hi) {
    u64 d;
    asm("mov.b64 %0, {%1, %2};" : "=l"(d) : "f"(lo), "f"(hi));
    return d;
}
__device__ __forceinline__ float2 unpack2(u64 v) {
    float2 r;
    asm("mov.b64 {%0, %1}, %2;" : "=f"(r.x), "=f"(r.y) : "l"(v));
    return r;
}

// ---------------------------------------------------------------------------
// K1 (fp16 tensor-core): X[4096,64] @ W_all[64,2048].
// Block = (rb: 64 rows, cb: 256 cols = one (t, part) slice). t=cb>>1, part=cb&1.
// A = fp16(x tile) [64][72]; B = fp16(w1 slice) [k=64][col=256 pad 264].
// Warp = 32-col group: 64M x 32N x 64K via ldmatrix + mma.m16n8k16.
// Epilogue: +b1 (part=1), cvt fp16, scattered half2 stores to g_Pa / g_Pb.
// ---------------------------------------------------------------------------
__global__ void __launch_bounds__(256) k1_proj(const float* __restrict__ x,
                                               const float* __restrict__ w1,
                                               const float* __restrict__ b1) {
    __shared__ __half sX[64 * 72];
    __shared__ __half sW[64 * 264];
    __shared__ float sb[256];
    const int tid = threadIdx.x;
    const int lane = tid & 31, wid = tid >> 5;
    const int rb = blockIdx.y, cb = blockIdx.x;
    const int t = cb >> 1, part = cb & 1;

    // stage x tile (fp32 -> fp16)
    const float4* x4 = (const float4*)x + rb * 1024;
#pragma unroll
    for (int i = 0; i < 4; i++) {
        int idx = i * 256 + tid;          // 1024 float4
        int row = idx >> 4, c4 = idx & 15;
        float4 v = x4[idx];
        __half2 h01 = __floats2half2_rn(v.x, v.y);
        __half2 h23 = __floats2half2_rn(v.z, v.w);
        __half2* dst = (__half2*)(sX + row * 72 + c4 * 4);
        dst[0] = h01; dst[1] = h23;
    }
    // stage w1 slice [k=64][h=256] (fp32 -> fp16)
    const float4* w4 = (const float4*)w1 + (t * 128 + part * 64) * 64;
#pragma unroll
    for (int i = 0; i < 16; i++) {
        int idx = i * 256 + tid;          // 4096 float4
        int k = idx >> 6, h4 = idx & 63;
        float4 v = w4[idx];
        __half2 h01 = __floats2half2_rn(v.x, v.y);
        __half2 h23 = __floats2half2_rn(v.z, v.w);
        __half2* dst = (__half2*)(sW + k * 264 + h4 * 4);
        dst[0] = h01; dst[1] = h23;
    }
    sb[tid] = part ? b1[t * 256 + tid] : 0.f;
    __syncthreads();

    const int g4 = lane >> 2, t4 = lane & 3;
    const int nbase = wid * 32;
    const u32 sX_u = (u32)__cvta_generic_to_shared(sX);
    const u32 sW_u = (u32)__cvta_generic_to_shared(sW);
    const u32 aAddr = sX_u +
        (u32)((((lane & 7) + ((lane >> 3) & 1) * 8) * 72 + (lane >> 4) * 8) * 2);
    const u32 bAddr = sW_u + (u32)(((lane & 15) * 264 + nbase) * 2);

    float c[16][4];
#pragma unroll
    for (int i = 0; i < 16; i++)
#pragma unroll
        for (int j = 0; j < 4; j++) c[i][j] = 0.f;

#pragma unroll
    for (int kc = 0; kc < 4; kc++) {
        u32 bf[4][2];
#pragma unroll
        for (int nt = 0; nt < 4; nt++) {
            u32 addr = bAddr + (u32)((kc * 16 * 264 + nt * 8) * 2);
            asm volatile("ldmatrix.sync.aligned.m8n8.x2.trans.shared.b16 {%0,%1}, [%2];"
                         : "=r"(bf[nt][0]), "=r"(bf[nt][1]) : "r"(addr));
        }
#pragma unroll
        for (int mt = 0; mt < 4; mt++) {
            u32 a[4];
            u32 addr = aAddr + (u32)((mt * 16 * 72 + kc * 16) * 2);
            asm volatile("ldmatrix.sync.aligned.m8n8.x4.shared.b16 {%0,%1,%2,%3}, [%4];"
                         : "=r"(a[0]), "=r"(a[1]), "=r"(a[2]), "=r"(a[3]) : "r"(addr));
#pragma unroll
            for (int nt = 0; nt < 4; nt++)
                mma_f16(c[mt * 4 + nt], a, bf[nt]);
        }
    }

    __half* base = (part ? g_Pb : g_Pa) + (t * 4096 + rb * 64) * 256;
#pragma unroll
    for (int mt = 0; mt < 4; mt++) {
#pragma unroll
        for (int nt = 0; nt < 4; nt++) {
            const float* cc = c[mt * 4 + nt];
            int col = nbase + nt * 8 + 2 * t4;
            float bb0 = sb[col], bb1 = sb[col + 1];
            int row0 = mt * 16 + g4;
            __half2 v0 = __floats2half2_rn(cc[0] + bb0, cc[1] + bb1);
            __half2 v1 = __floats2half2_rn(cc[2] + bb0, cc[3] + bb1);
            *(__half2*)(base + row0 * 256 + col) = v0;
            *(__half2*)(base + (row0 + 8) * 256 + col) = v1;
        }
    }
}

// ---------------------------------------------------------------------------
// K2 (dominant, fp16 tensor-core, 512 threads): block = (b, 4 receivers),
// loops t(4). sA [256 rows][264] half = relu(Pa[s]+Pb[r]); sB [256][72] half.
// Warp (r_local = wid&3, nq = wid>>2): 64M x 16N x 256K. Epilogue:
// relu(C+b2)*rel_type, shuffle-reduce over senders, register accumulate
// across t; one plain float2 store / owning lane at the end.
// ---------------------------------------------------------------------------
#define SA_K 264
#define SB_O 72
#define K2_SMEM (256 * SA_K * 2 + 256 * SB_O * 2 + 256 * 4 + 64 * 4)

__global__ void __launch_bounds__(512) k2_edge(const float* __restrict__ rel_type,
                                               const float* __restrict__ w2,
                                               const float* __restrict__ b2) {
    extern __shared__ __align__(16) char smraw[];
    __half* sA = (__half*)smraw;                              // [256][SA_K]
    __half* sB = (__half*)(smraw + 256 * SA_K * 2);           // [256][SB_O]
    float* rt_sm = (float*)(smraw + 256 * SA_K * 2 + 256 * SB_O * 2);  // [4][64]
    float* b2s = rt_sm + 256;                                 // [64]

    const int tid = threadIdx.x;
    const int lane = tid & 31, wid = tid >> 5;
    const int b = blockIdx.y, rbase = blockIdx.x * 4;
    const int r_local = wid & 3;      // receiver owned by this warp
    const int nq = wid >> 2;          // 16-col quarter of the 64 outputs
    const int g4 = lane >> 2, t4 = lane & 3;

    const u32 sA_u = (u32)__cvta_generic_to_shared(sA);
    const u32 sB_u = (u32)__cvta_generic_to_shared(sB);
    const u32 aAddr = sA_u +
        (u32)(((r_local * 64 + (lane & 7) + ((lane >> 3) & 1) * 8) * SA_K +
               (lane >> 4) * 8) * 2);
    const u32 bAddr = sB_u + (u32)(((lane & 15) * SB_O + nq * 16) * 2);

    float racc[2][2];
#pragma unroll
    for (int nt = 0; nt < 2; nt++) { racc[nt][0] = 0.f; racc[nt][1] = 0.f; }

    const __half2 z2 = __float2half2_rn(0.f);

    for (int t = 0; t < 4; t++) {
        __syncthreads();   // previous iteration's mma/epilogue done

        // ---- stage sB = fp16(w2[t]) as [k][o] ----
        const float4* w2t4 = (const float4*)(w2 + t * 16384);
#pragma unroll
        for (int i = 0; i < 8; i++) {
            int idx = i * 512 + tid;            // 4096 float4
            int k = idx >> 4, o4 = idx & 15;
            float4 w = w2t4[idx];
            __half2 h01 = __floats2half2_rn(w.x, w.y);
            __half2 h23 = __floats2half2_rn(w.z, w.w);
            __half2* dst = (__half2*)(sB + k * SB_O + o4 * 4);
            dst[0] = h01; dst[1] = h23;
        }
        // ---- stage rel_type for 4 receivers x 64 senders ----
        if (tid < 256) {
            int s = tid & 63, rl = tid >> 6;
            int r = rbase + rl;
            float v = 0.f;
            if (s != r) v = rel_type[(b * 4032 + s * 63 + r - (r > s ? 1 : 0)) * 4 + t];
            rt_sm[rl * 64 + s] = v;
        }
        if (tid < 64) b2s[tid] = b2[t * 64 + tid];

        // ---- build sA: row = rl*64+s, relu(Pa[s] + Pb[rbase+rl]) in fp16 ----
        const __half* PaH = g_Pa + (t * 4096 + b * 64) * 256;
        const __half* PbH = g_Pb + (t * 4096 + b * 64) * 256;
#pragma unroll
        for (int i = 0; i < 16; i++) {
            int grp = i * 512 + tid;            // 8192 groups of 8 halves
            int row = grp >> 5, c8 = grp & 31;
            int s = row & 63, rl = row >> 6;
            uint4 pa = *(const uint4*)(PaH + s * 256 + c8 * 8);
            uint4 pb = *(const uint4*)(PbH + (rbase + rl) * 256 + c8 * 8);
            uint4 o;
            __half2 v;
            v = __hmax2(__hadd2(*(__half2*)&pa.x, *(__half2*)&pb.x), z2); o.x = *(u32*)&v;
            v = __hmax2(__hadd2(*(__half2*)&pa.y, *(__half2*)&pb.y), z2); o.y = *(u32*)&v;
            v = __hmax2(__hadd2(*(__half2*)&pa.z, *(__half2*)&pb.z), z2); o.z = *(u32*)&v;
            v = __hmax2(__hadd2(*(__half2*)&pa.w, *(__half2*)&pb.w), z2); o.w = *(u32*)&v;
            *(uint4*)(sA + row * SA_K + c8 * 8) = o;
        }
        __syncthreads();

        // ---- 64x16x256 warp GEMM: 4mt x 2nt m16n8k16 tiles, 16 k-chunks ----
        float c[8][4];
#pragma unroll
        for (int i = 0; i < 8; i++)
#pragma unroll
            for (int j = 0; j < 4; j++) c[i][j] = 0.f;

#pragma unroll
        for (int kc = 0; kc < 16; kc++) {
            u32 bf[2][2];
#pragma unroll
            for (int nt = 0; nt < 2; nt++) {
                u32 addr = bAddr + (u32)((kc * 16 * SB_O + nt * 8) * 2);
                asm volatile(
                    "ldmatrix.sync.aligned.m8n8.x2.trans.shared.b16 {%0,%1}, [%2];"
                    : "=r"(bf[nt][0]), "=r"(bf[nt][1]) : "r"(addr));
            }
#pragma unroll
            for (int mt = 0; mt < 4; mt++) {
                u32 a[4];
                u32 addr = aAddr + (u32)((mt * 16 * SA_K + kc * 16) * 2);
                asm volatile(
                    "ldmatrix.sync.aligned.m8n8.x4.shared.b16 {%0,%1,%2,%3}, [%4];"
                    : "=r"(a[0]), "=r"(a[1]), "=r"(a[2]), "=r"(a[3]) : "r"(addr));
#pragma unroll
                for (int nt = 0; nt < 2; nt++)
                    mma_f16(c[mt * 2 + nt], a, bf[nt]);
            }
        }

        // ---- epilogue: relu(C + b2)*rt, reduce over senders, accum in regs ----
        float rtv[4][2];
#pragma unroll
        for (int mt = 0; mt < 4; mt++) {
            rtv[mt][0] = rt_sm[r_local * 64 + mt * 16 + g4];
            rtv[mt][1] = rt_sm[r_local * 64 + mt * 16 + g4 + 8];
        }
#pragma unroll
        for (int nt = 0; nt < 2; nt++) {
            int col = nq * 16 + nt * 8 + 2 * t4;
            float bb0 = b2s[col], bb1 = b2s[col + 1];
            float p0 = 0.f, p1 = 0.f;
#pragma unroll
            for (int mt = 0; mt < 4; mt++) {
                const float* cc = c[mt * 2 + nt];
                p0 += fmaxf(cc[0] + bb0, 0.f) * rtv[mt][0];
                p1 += fmaxf(cc[1] + bb1, 0.f) * rtv[mt][0];
                p0 += fmaxf(cc[2] + bb0, 0.f) * rtv[mt][1];
                p1 += fmaxf(cc[3] + bb1, 0.f) * rtv[mt][1];
            }
#pragma unroll
            for (int off = 4; off < 32; off <<= 1) {
                p0 += __shfl_xor_sync(0xffffffffu, p0, off);
                p1 += __shfl_xor_sync(0xffffffffu, p1, off);
            }
            racc[nt][0] += p0;
            racc[nt][1] += p1;
        }
    }

    // ---- final store: each (b, r, col) owned by exactly one warp ----
    if (lane < 4) {   // g4 == 0 lanes, t4 = lane
        float* dst = g_agg + (b * 64 + rbase + r_local) * 64 + nq * 16 + 2 * t4;
#pragma unroll
        for (int nt = 0; nt < 2; nt++)
            *(float2*)(dst + nt * 8) = make_float2(racc[nt][0], racc[nt][1]);
    }
}

// ---------------------------------------------------------------------------
// K3: output MLP, f32x2 packed fma, 128 blocks x 32 rows, 256 threads.
// ---------------------------------------------------------------------------
#define HPAD 260
#define K3_SMEM ((32 * 128 + 2 * 32 * HPAD) * 4)

__global__ void __launch_bounds__(256) k3_out(const float* __restrict__ x,
                                              const float* __restrict__ ow1,
                                              const float* __restrict__ ob1,
                                              const float* __restrict__ ow2,
                                              const float* __restrict__ ob2,
                                              const float* __restrict__ ow3,
                                              const float* __restrict__ ob3,
                                              float* __restrict__ out) {
    extern __shared__ __align__(16) float sm3[];
    float* sAug = sm3;                 // [32][128]
    float* sH = sm3 + 32 * 128;        // [32][HPAD]
    float* sH2 = sH + 32 * HPAD;       // [32][HPAD]
    const int tid = threadIdx.x;
    const int base = blockIdx.x * 32;

#pragma unroll
    for (int i = 0; i < 16; i++) {
        int idx = tid + i * 256;           // 4096
        int row = idx >> 7, c = idx & 127;
        float v = (c < 64) ? x[(base + row) * 64 + c]
                           : g_agg[(base + row) * 64 + (c - 64)];
        sAug[idx] = v;
    }
    __syncthreads();

    const int cg = tid & 63, rg = tid >> 6;   // 64 col-groups x 4 row-groups(8 rows)

    {   // stage 1: 128 -> 256
        u64 acc[8][2];
#pragma unroll
        for (int r = 0; r < 8; r++) { acc[r][0] = 0ull; acc[r][1] = 0ull; }
#pragma unroll 4
        for (int k = 0; k < 128; k++) {
            float4 w = *((const float4*)(ow1 + k * 256) + cg);
            u64 w01 = pack2(w.x, w.y), w23 = pack2(w.z, w.w);
#pragma unroll
            for (int r = 0; r < 8; r++) {
                u64 a = dup2(sAug[(rg * 8 + r) * 128 + k]);
                acc[r][0] = ffma2(a, w01, acc[r][0]);
                acc[r][1] = ffma2(a, w23, acc[r][1]);
            }
        }
        float4 bb = *((const float4*)ob1 + cg);
#pragma unroll
        for (int r = 0; r < 8; r++) {
            float2 v01 = unpack2(acc[r][0]), v23 = unpack2(acc[r][1]);
            float* dst = sH + (rg * 8 + r) * HPAD + cg * 4;
            dst[0] = fmaxf(v01.x + bb.x, 0.f);
            dst[1] = fmaxf(v01.y + bb.y, 0.f);
            dst[2] = fmaxf(v23.x + bb.z, 0.f);
            dst[3] = fmaxf(v23.y + bb.w, 0.f);
        }
    }
    __syncthreads();

    {   // stage 2: 256 -> 256
        u64 acc[8][2];
#pragma unroll
        for (int r = 0; r < 8; r++) { acc[r][0] = 0ull; acc[r][1] = 0ull; }
#pragma unroll 4
        for (int k = 0; k < 256; k++) {
            float4 w = *((const float4*)(ow2 + k * 256) + cg);
            u64 w01 = pack2(w.x, w.y), w23 = pack2(w.z, w.w);
#pragma unroll
            for (int r = 0; r < 8; r++) {
                u64 a = dup2(sH[(rg * 8 + r) * HPAD + k]);
                acc[r][0] = ffma2(a, w01, acc[r][0]);
                acc[r][1] = ffma2(a, w23, acc[r][1]);
            }
        }
        float4 bb = *((const float4*)ob2 + cg);
#pragma unroll
        for (int r = 0; r < 8; r++) {
            float2 v01 = unpack2(acc[r][0]), v23 = unpack2(acc[r][1]);
            float* dst = sH2 + (rg * 8 + r) * HPAD + cg * 4;
            dst[0] = fmaxf(v01.x + bb.x, 0.f);
            dst[1] = fmaxf(v01.y + bb.y, 0.f);
            dst[2] = fmaxf(v23.x + bb.z, 0.f);
            dst[3] = fmaxf(v23.y + bb.w, 0.f);
        }
    }
    __syncthreads();

    {   // stage 3: 256 -> 64 (fp32, full precision on the final layer)
        const int cg2 = tid & 15, rt = tid >> 4;   // 16 col-groups x 16, 2 rows each
        u64 acc[2][2];
        acc[0][0] = acc[0][1] = acc[1][0] = acc[1][1] = 0ull;
#pragma unroll 4
        for (int k = 0; k < 256; k++) {
            float4 w = *((const float4*)(ow3 + k * 64) + cg2);
            u64 w01 = pack2(w.x, w.y), w23 = pack2(w.z, w.w);
            u64 a0 = dup2(sH2[rt * HPAD + k]);
            u64 a1 = dup2(sH2[(rt + 16) * HPAD + k]);
            acc[0][0] = ffma2(a0, w01, acc[0][0]);
            acc[0][1] = ffma2(a0, w23, acc[0][1]);
            acc[1][0] = ffma2(a1, w01, acc[1][0]);
            acc[1][1] = ffma2(a1, w23, acc[1][1]);
        }
        float4 bb = *((const float4*)ob3 + cg2);
#pragma unroll
        for (int rr = 0; rr < 2; rr++) {
            float2 v01 = unpack2(acc[rr][0]), v23 = unpack2(acc[rr][1]);
            float4 v = make_float4(v01.x + bb.x, v01.y + bb.y,
                                   v23.x + bb.z, v23.y + bb.w);
            *((float4*)(out + (base + rt + rr * 16) * 64) + cg2) = v;
        }
    }
}

// ---------------------------------------------------------------------------
extern "C" void kernel_launch(void* const* d_in, const int* in_sizes, int n_in,
                              void* d_out, int out_size) {
    const float* x        = (const float*)d_in[0];
    const float* rel_type = (const float*)d_in[1];
    // d_in[2]=rel_rec, d_in[3]=rel_send: structure is analytic, unused
    const float* w1  = (const float*)d_in[4];
    const float* b1  = (const float*)d_in[5];
    const float* w2  = (const float*)d_in[6];
    const float* b2  = (const float*)d_in[7];
    const float* ow1 = (const float*)d_in[8];
    const float* ob1 = (const float*)d_in[9];
    const float* ow2 = (const float*)d_in[10];
    const float* ob2 = (const float*)d_in[11];
    const float* ow3 = (const float*)d_in[12];
    const float* ob3 = (const float*)d_in[13];
    float* out = (float*)d_out;

    cudaFuncSetAttribute(k2_edge, cudaFuncAttributeMaxDynamicSharedMemorySize, K2_SMEM);
    cudaFuncSetAttribute(k3_out, cudaFuncAttributeMaxDynamicSharedMemorySize, K3_SMEM);

    k1_proj<<<dim3(8, 64), 256>>>(x, w1, b1);
    k2_edge<<<dim3(16, 64), 512, K2_SMEM>>>(rel_type, w2, b2);
    k3_out<<<128, 256, K3_SMEM>>>(x, ow1, ob1, ow2, ob2, ow3, ob3, out);
}